// round 12
// baseline (speedup 1.0000x reference)
#include <cuda_runtime.h>
#include <cuda_fp16.h>
#include <math.h>
#include <stdint.h>

#define BATCH   262144
#define DD      100
#define KP      416       // padded K (fp16 cols): 404 -> 416 (last chunk = 32 real cols)
#define NP      400       // interleaved gate rows: 100 quadruples (r,z,n,hn)
#define BMM     128
#define BNN     80
#define NCHUNK  7         // 6 full 64-col chunks + 1 half (32-col) chunk
#define XLP     104       // packed X_lo width (h cols only)

// -------- device scratch --------
__device__ __half g_Xhi[(size_t)BATCH * KP];
__device__ __half g_Xlo[(size_t)BATCH * XLP];  // packed: cols 304..403 of X (for exact h)
__device__ __half g_Whi[(size_t)NP * KP];
__device__ __half g_W1h[64 * 128];             // W1 fp16, K padded to 128
__device__ float g_bq[NP];
__device__ __half g_HNh[(size_t)BATCH * 128];  // h_new fp16, 128-col padded
__device__ __half g_Ah[(size_t)BATCH * 64];    // relu(...) fp16
__device__ float g_stats[128];
__device__ float g_W2e[128];
__device__ float g_be[2];

__device__ __forceinline__ uint32_t smem_u32(const void* p) {
    uint32_t a;
    asm("{ .reg .u64 t; cvta.to.shared.u64 t, %1; cvt.u32.u64 %0, t; }" : "=r"(a) : "l"(p));
    return a;
}
#define LDSM4(r, a) asm volatile("ldmatrix.sync.aligned.m8n8.x4.shared.b16 {%0,%1,%2,%3}, [%4];" \
    : "=r"((r)[0]), "=r"((r)[1]), "=r"((r)[2]), "=r"((r)[3]) : "r"(a))
#define LDSM2(r, a) asm volatile("ldmatrix.sync.aligned.m8n8.x2.shared.b16 {%0,%1}, [%2];" \
    : "=r"((r)[0]), "=r"((r)[1]) : "r"(a))
#define MMA(c, a, b) asm volatile( \
    "mma.sync.aligned.m16n8k16.row.col.f32.f16.f16.f32 {%0,%1,%2,%3},{%4,%5,%6,%7},{%8,%9},{%0,%1,%2,%3};" \
    : "+f"((c)[0]), "+f"((c)[1]), "+f"((c)[2]), "+f"((c)[3])                                                \
    : "r"((a)[0]), "r"((a)[1]), "r"((a)[2]), "r"((a)[3]), "r"((b)[0]), "r"((b)[1]))
__device__ __forceinline__ void cpa16(uint32_t d, const void* s) {
    asm volatile("{ .reg .u64 g; cvta.to.global.u64 g, %1; cp.async.cg.shared.global [%0], [g], 16; }"
                 :: "r"(d), "l"(s));
}
#define CPA_COMMIT() asm volatile("cp.async.commit_group;" ::: "memory")

// fast accurate cos: own Cody-Waite reduction (arg |x| < ~1e5) + __cosf on [-pi,pi]
__device__ __forceinline__ float fast_cos(float a) {
    float k = rintf(a * 0.15915494309189535f);
    float r = fmaf(k, -6.2831854820251465f, a);   // 2pi hi (exact fma)
    r = fmaf(k, 1.7484555e-7f, r);                // -(2pi - hi)
    return __cosf(r);
}

// gemm smem: 3 stages of 26KB, then bias
#define STAGE_SZ 26624
#define SBIAS    79872
#define SMEM_TOT 80256
// w1bn smem
#define WSM_B1   49152
#define WSM_S    49408
#define WSM_Q    49664
#define WSM_TOT  49920

// ===================== K0: prep interleaved weights (fp16) =====================
__global__ __launch_bounds__(256) void prep_kernel(const float* __restrict__ W_ih,
                                                   const float* __restrict__ W_hh,
                                                   const float* __restrict__ b_ih,
                                                   const float* __restrict__ b_hh,
                                                   const float* __restrict__ W1) {
    int idx = blockIdx.x * 256 + threadIdx.x;
    if (idx < NP * KP) {
        int r = idx / KP, k = idx % KP;
        int d = r >> 2, g = r & 3;
        float v = 0.f;
        if (g == 0) {
            if (k < 304)      v = W_ih[d * 304 + k];
            else if (k < 404) v = W_hh[d * 100 + (k - 304)];
        } else if (g == 1) {
            int rr = 100 + d;
            if (k < 304)      v = W_ih[rr * 304 + k];
            else if (k < 404) v = W_hh[rr * 100 + (k - 304)];
        } else if (g == 2) {
            if (k < 304)      v = W_ih[(200 + d) * 304 + k];
        } else {
            if (k >= 304 && k < 404) v = W_hh[(200 + d) * 100 + (k - 304)];
        }
        g_Whi[idx] = __float2half(v);
    }
    if (idx < 64 * 128) {
        int n = idx >> 7, k = idx & 127;
        g_W1h[idx] = __float2half(k < 100 ? W1[n * 100 + k] : 0.f);
    }
    if (idx < NP) {
        int d = idx >> 2, g = idx & 3;
        float bv;
        if (g == 0)      bv = b_ih[d] + b_hh[d];
        else if (g == 1) bv = b_ih[100 + d] + b_hh[100 + d];
        else if (g == 2) bv = b_ih[200 + d];
        else             bv = b_hh[200 + d];
        g_bq[idx] = bv;
    }
    if (idx < 128) g_stats[idx] = 0.f;
}

// ===================== K1: gather + assemble X (vectorized, fast cos) ==========
__global__ __launch_bounds__(256) void assemble_kernel(const int*   __restrict__ n_id,
                                                       const float* __restrict__ memory,
                                                       const int*   __restrict__ last_update,
                                                       const int*   __restrict__ store_src,
                                                       const int*   __restrict__ store_dst,
                                                       const int*   __restrict__ store_t,
                                                       const float* __restrict__ store_msg,
                                                       const float* __restrict__ time_w,
                                                       const float* __restrict__ time_b) {
    int w = threadIdx.x >> 5, lane = threadIdx.x & 31;
    int b = blockIdx.x * 8 + w;
    int n   = n_id[b];
    int src = store_src[n];
    int dst = store_dst[n];
    float dt = (float)(store_t[n] - last_update[n]);
    const float2* ms2 = (const float2*)(memory + (size_t)src * DD);   // 8B aligned (100*src even)
    const float2* md2 = (const float2*)(memory + (size_t)dst * DD);
    const float2* mn2 = (const float2*)(memory + (size_t)n   * DD);
    const float2* mg2 = (const float2*)(store_msg + (size_t)n * 4);
    const float2* tw2 = (const float2*)time_w;
    const float2* tb2 = (const float2*)time_b;
    __half2* xh2 = (__half2*)(g_Xhi + (size_t)b * KP);
    __half2* xl2 = (__half2*)(g_Xlo + (size_t)b * XLP);
    // 208 half2 columns: [0,50) ms | [50,100) md | [100,102) msg | [102,152) tenc
    //                    | [152,202) h=mn | [202,208) zero
    #pragma unroll
    for (int it = 0; it < 7; it++) {
        int c2 = it * 32 + lane;
        if (c2 >= 208) break;
        float2 v;
        bool is_h = false;
        if (c2 < 50)        v = ms2[c2];
        else if (c2 < 100)  v = md2[c2 - 50];
        else if (c2 < 102)  v = mg2[c2 - 100];
        else if (c2 < 152) {
            int j = c2 - 102;
            float2 tw = tw2[j], tb = tb2[j];
            float a0 = __fadd_rn(__fmul_rn(dt, tw.x), tb.x);  // no fma (match jax)
            float a1 = __fadd_rn(__fmul_rn(dt, tw.y), tb.y);
            v.x = fast_cos(a0);
            v.y = fast_cos(a1);
        }
        else if (c2 < 202) { v = mn2[c2 - 152]; is_h = true; }
        else                v = make_float2(0.f, 0.f);
        __half2 h2 = __floats2half2_rn(v.x, v.y);
        xh2[c2] = h2;
        if (is_h) {
            float2 back = __half22float2(h2);
            xl2[c2 - 152] = __floats2half2_rn(v.x - back.x, v.y - back.y);
        }
    }
}

// ===================== K2: HMMA GEMM (3-stage, ks-pipelined frags) + GRU ====
struct Frag { uint32_t ah[2][4]; uint32_t bh[5][2]; };

__device__ __forceinline__ void load_frags(Frag& f, uint32_t st, int ks, int wm0, int wn0, int lane) {
    int arow = wm0 + (lane & 7) + ((lane >> 3) & 1) * 8;
    int achk = 2 * ks + (lane >> 4);
    #pragma unroll
    for (int i = 0; i < 2; i++) {
        int r = arow + i * 16;
        LDSM4(f.ah[i], st + r * 128 + ((achk ^ (r & 7)) << 4));
    }
    int rr = wn0 + (lane & 7);
    int chk2 = 2 * ks + ((lane >> 3) & 1);
    #pragma unroll
    for (int jp = 0; jp < 2; jp++) {
        int r = rr + (jp * 2 + (lane >> 4)) * 8;
        uint32_t off = r * 128 + ((chk2 ^ (r & 7)) << 4);
        uint32_t t4[4];
        LDSM4(t4, st + 16384 + off);
        f.bh[jp*2][0]   = t4[0]; f.bh[jp*2][1]   = t4[1];
        f.bh[jp*2+1][0] = t4[2]; f.bh[jp*2+1][1] = t4[3];
    }
    int r = rr + 32;
    uint32_t off = r * 128 + ((chk2 ^ (r & 7)) << 4);
    LDSM2(f.bh[4], st + 16384 + off);
}

__global__ __launch_bounds__(256, 2) void gemm_kernel() {
    extern __shared__ char sm[];
    const uint32_t sb = smem_u32(sm);
    const int tid = threadIdx.x, wid = tid >> 5, lane = tid & 31;
    const int nt = blockIdx.x;            // N-tile fastest -> A reuse in L2
    const int m0 = blockIdx.y * BMM;
    const int n0 = nt * BNN;
    const int wm0 = (wid & 3) * 32;
    const int wn0 = (wid >> 2) * 40;

    if (tid < BNN) ((float*)(sm + SBIAS))[tid] = g_bq[n0 + tid];

    float c[2][5][4];
    #pragma unroll
    for (int i = 0; i < 2; i++)
        #pragma unroll
        for (int j = 0; j < 5; j++)
            #pragma unroll
            for (int q = 0; q < 4; q++) c[i][j][q] = 0.f;

    auto stage = [&](int ch, uint32_t base) {
        #pragma unroll 1
        for (int i = tid; i < 1664; i += 256) {
            int j = i & 7;
            if (ch == 6 && j >= 4) continue;
            uint32_t dst;
            const char* src;
            if (i < 1024) {
                int r = i >> 3;
                src = (const char*)g_Xhi + (size_t)(m0 + r) * (KP * 2) + ch * 128 + j * 16;
                dst = base + r * 128 + ((j ^ (r & 7)) << 4);
            } else {
                int r = (i - 1024) >> 3;
                src = (const char*)g_Whi + (size_t)(n0 + r) * (KP * 2) + ch * 128 + j * 16;
                dst = base + 16384 + r * 128 + ((j ^ (r & 7)) << 4);
            }
            cpa16(dst, src);
        }
        CPA_COMMIT();
    };

    stage(0, sb);
    stage(1, sb + STAGE_SZ);

    uint32_t stoff[3] = {0u, STAGE_SZ, 2u * STAGE_SZ};
    Frag fr[2];

    for (int ch = 0; ch < NCHUNK; ch++) {
        if (ch < NCHUNK - 1) asm volatile("cp.async.wait_group 1;" ::: "memory");
        else                 asm volatile("cp.async.wait_group 0;" ::: "memory");
        __syncthreads();
        if (ch + 2 < NCHUNK) stage(ch + 2, sb + stoff[(ch + 2) % 3]);  // overlaps compute(ch)
        const uint32_t st = sb + stoff[ch % 3];
        const int nks = (ch == NCHUNK - 1) ? 2 : 4;
        load_frags(fr[0], st, 0, wm0, wn0, lane);
        for (int ks = 0; ks < nks; ks++) {
            int cur = ks & 1;
            if (ks + 1 < nks) load_frags(fr[cur ^ 1], st, ks + 1, wm0, wn0, lane);
            #pragma unroll
            for (int i = 0; i < 2; i++)
                #pragma unroll
                for (int j = 0; j < 5; j++)
                    MMA(c[i][j], fr[cur].ah[i], fr[cur].bh[j]);
        }
    }
    __syncthreads();

    // stage C (+bias) into smem: 128 x 84 floats
    float* Cs = (float*)sm;
    const float* sbias = (const float*)(sm + SBIAS);
    #pragma unroll
    for (int i = 0; i < 2; i++) {
        int r0 = wm0 + i * 16 + (lane >> 2);
        #pragma unroll
        for (int j = 0; j < 5; j++) {
            int cc = wn0 + j * 8 + 2 * (lane & 3);
            float bz0 = sbias[cc], bz1 = sbias[cc + 1];
            Cs[r0 * 84 + cc]           = c[i][j][0] + bz0;
            Cs[r0 * 84 + cc + 1]       = c[i][j][1] + bz1;
            Cs[(r0 + 8) * 84 + cc]     = c[i][j][2] + bz0;
            Cs[(r0 + 8) * 84 + cc + 1] = c[i][j][3] + bz1;
        }
    }
    __syncthreads();

    // fused GRU epilogue: 128 rows x 20 quadruples -> fp16 h_new
    for (int g = tid; g < 128 * 20; g += 256) {
        int m = g / 20, dl = g % 20;
        float4 v = *(const float4*)&Cs[m * 84 + 4 * dl];
        int dg = nt * 20 + dl;
        int mg = m0 + m;
        float h = __half2float(g_Xhi[(size_t)mg * KP + 304 + dg]) +
                  __half2float(g_Xlo[(size_t)mg * XLP + dg]);
        float rr = 1.f / (1.f + __expf(-v.x));
        float zz = 1.f / (1.f + __expf(-v.y));
        float nn = tanhf(v.z + rr * v.w);
        g_HNh[(size_t)mg * 128 + dg] = __float2half((1.f - zz) * nn + zz * h);
    }
}

// ===================== K3: HMMA A = relu(HN @ W1^T + b1) + BN stats =============
__global__ __launch_bounds__(256) void w1bn_kernel(const float* __restrict__ b1) {
    extern __shared__ char wsm[];
    const uint32_t sb = smem_u32(wsm);
    const int tid = threadIdx.x, wid = tid >> 5, lane = tid & 31;
    const int m0 = blockIdx.x * 128;
    const int wm0 = (wid & 3) * 32;
    const int wn0 = (wid >> 2) * 32;
    float* b1s  = (float*)(wsm + WSM_B1);
    float* sacc = (float*)(wsm + WSM_S);
    float* qacc = (float*)(wsm + WSM_Q);
    if (tid < 64) { b1s[tid] = b1[tid]; sacc[tid] = 0.f; qacc[tid] = 0.f; }

    #pragma unroll 1
    for (int i = tid; i < 3072; i += 256) {
        uint32_t dst;
        const char* src;
        if (i < 2048) {
            int ch = i >> 10, ii = i & 1023, r = ii >> 3, j = ii & 7;
            src = (const char*)g_HNh + (size_t)(m0 + r) * 256 + ch * 128 + j * 16;
            dst = sb + ch * 16384 + r * 128 + ((j ^ (r & 7)) << 4);
        } else {
            int ii = i - 2048;
            int ch = ii >> 9, i2 = ii & 511, r = i2 >> 3, j = i2 & 7;
            src = (const char*)g_W1h + (size_t)r * 256 + ch * 128 + j * 16;
            dst = sb + 32768 + ch * 8192 + r * 128 + ((j ^ (r & 7)) << 4);
        }
        cpa16(dst, src);
    }
    CPA_COMMIT();
    asm volatile("cp.async.wait_group 0;" ::: "memory");
    __syncthreads();

    float c[2][4][4];
    #pragma unroll
    for (int i = 0; i < 2; i++)
        #pragma unroll
        for (int j = 0; j < 4; j++)
            #pragma unroll
            for (int q = 0; q < 4; q++) c[i][j][q] = 0.f;

    #pragma unroll
    for (int ks = 0; ks < 8; ks++) {
        int ch = ks >> 2, kk = ks & 3;
        uint32_t ah[2][4], bh[4][2];
        int arow = wm0 + (lane & 7) + ((lane >> 3) & 1) * 8;
        int achk = 2 * kk + (lane >> 4);
        #pragma unroll
        for (int i = 0; i < 2; i++) {
            int r = arow + i * 16;
            LDSM4(ah[i], sb + ch * 16384 + r * 128 + ((achk ^ (r & 7)) << 4));
        }
        int rr = wn0 + (lane & 7);
        int chk2 = 2 * kk + ((lane >> 3) & 1);
        #pragma unroll
        for (int jp = 0; jp < 2; jp++) {
            int r = rr + (jp * 2 + (lane >> 4)) * 8;
            uint32_t off = r * 128 + ((chk2 ^ (r & 7)) << 4);
            uint32_t t4[4];
            LDSM4(t4, sb + 32768 + ch * 8192 + off);
            bh[jp*2][0]   = t4[0]; bh[jp*2][1]   = t4[1];
            bh[jp*2+1][0] = t4[2]; bh[jp*2+1][1] = t4[3];
        }
        #pragma unroll
        for (int i = 0; i < 2; i++)
            #pragma unroll
            for (int j = 0; j < 4; j++)
                MMA(c[i][j], ah[i], bh[j]);
    }

    #pragma unroll
    for (int j = 0; j < 4; j++) {
        int col = wn0 + j * 8 + 2 * (lane & 3);
        float bz0 = b1s[col], bz1 = b1s[col + 1];
        float s0 = 0.f, q0 = 0.f, s1 = 0.f, q1 = 0.f;
        #pragma unroll
        for (int i = 0; i < 2; i++) {
            int row = m0 + wm0 + i * 16 + (lane >> 2);
            float a0 = fmaxf(c[i][j][0] + bz0, 0.f);
            float a1 = fmaxf(c[i][j][1] + bz1, 0.f);
            float a2 = fmaxf(c[i][j][2] + bz0, 0.f);
            float a3 = fmaxf(c[i][j][3] + bz1, 0.f);
            *(__half2*)&g_Ah[(size_t)row * 64 + col]       = __floats2half2_rn(a0, a1);
            *(__half2*)&g_Ah[(size_t)(row + 8) * 64 + col] = __floats2half2_rn(a2, a3);
            s0 += a0 + a2; q0 += a0 * a0 + a2 * a2;
            s1 += a1 + a3; q1 += a1 * a1 + a3 * a3;
        }
        #pragma unroll
        for (int off = 4; off <= 16; off <<= 1) {
            s0 += __shfl_xor_sync(0xffffffff, s0, off);
            q0 += __shfl_xor_sync(0xffffffff, q0, off);
            s1 += __shfl_xor_sync(0xffffffff, s1, off);
            q1 += __shfl_xor_sync(0xffffffff, q1, off);
        }
        if (lane < 4) {
            atomicAdd(&sacc[col], s0); atomicAdd(&qacc[col], q0);
            atomicAdd(&sacc[col + 1], s1); atomicAdd(&qacc[col + 1], q1);
        }
    }
    __syncthreads();
    if (tid < 64) {
        atomicAdd(&g_stats[tid],      sacc[tid]);
        atomicAdd(&g_stats[64 + tid], qacc[tid]);
    }
}

// ===================== K4: finalize BN, fold into W2 =====================
__global__ void finalize_kernel(const float* __restrict__ gamma,
                                const float* __restrict__ beta,
                                const float* __restrict__ W2,
                                const float* __restrict__ b2) {
    __shared__ float red0[64], red1[64];
    int j = threadIdx.x;
    float mu  = g_stats[j]      * (1.f / BATCH);
    float var = g_stats[64 + j] * (1.f / BATCH) - mu * mu;
    float inv = rsqrtf(var + 1e-5f);
    float gsc = gamma[j] * inv;
    float w0 = W2[j], w1 = W2[64 + j];
    g_W2e[2 * j]     = w0 * gsc;
    g_W2e[2 * j + 1] = w1 * gsc;
    float c = beta[j] - mu * gsc;
    red0[j] = c * w0;
    red1[j] = c * w1;
    __syncthreads();
    if (j == 0) { float s = 0.f; for (int i = 0; i < 64; i++) s += red0[i]; g_be[0] = b2[0] + s; }
    if (j == 1) { float s = 0.f; for (int i = 0; i < 64; i++) s += red1[i]; g_be[1] = b2[1] + s; }
}

// ===================== K5: output = A @ W2e + be =====================
__global__ __launch_bounds__(256) void out_kernel(float* __restrict__ out) {
    __shared__ float w2s[128];
    __shared__ float bes[2];
    int tid = threadIdx.x;
    if (tid < 128) w2s[tid] = g_W2e[tid];
    if (tid < 2)   bes[tid] = g_be[tid];
    __syncthreads();
    int b = blockIdx.x * 256 + tid;
    const __half2* ar = (const __half2*)(g_Ah + (size_t)b * 64);
    float o0 = bes[0], o1 = bes[1];
    #pragma unroll
    for (int q = 0; q < 32; q++) {
        float2 v = __half22float2(ar[q]);
        o0 += v.x * w2s[4 * q]     + v.y * w2s[4 * q + 2];
        o1 += v.x * w2s[4 * q + 1] + v.y * w2s[4 * q + 3];
    }
    ((float2*)out)[b] = make_float2(o0, o1);
}

// ===================== launcher =====================
extern "C" void kernel_launch(void* const* d_in, const int* in_sizes, int n_in,
                              void* d_out, int out_size) {
    const int*   n_id        = (const int*)  d_in[0];
    const float* memory      = (const float*)d_in[1];
    const int*   last_update = (const int*)  d_in[2];
    const int*   store_src   = (const int*)  d_in[3];
    const int*   store_dst   = (const int*)  d_in[4];
    const int*   store_t     = (const int*)  d_in[5];
    const float* store_msg   = (const float*)d_in[6];
    const float* time_w      = (const float*)d_in[7];
    const float* time_b      = (const float*)d_in[8];
    const float* W_ih        = (const float*)d_in[9];
    const float* b_ih        = (const float*)d_in[10];
    const float* W_hh        = (const float*)d_in[11];
    const float* b_hh        = (const float*)d_in[12];
    const float* W1          = (const float*)d_in[13];
    const float* b1          = (const float*)d_in[14];
    const float* gamma       = (const float*)d_in[15];
    const float* beta        = (const float*)d_in[16];
    const float* W2          = (const float*)d_in[17];
    const float* b2          = (const float*)d_in[18];
    float*       out         = (float*)d_out;

    cudaFuncSetAttribute(gemm_kernel, cudaFuncAttributeMaxDynamicSharedMemorySize, SMEM_TOT);
    cudaFuncSetAttribute(w1bn_kernel, cudaFuncAttributeMaxDynamicSharedMemorySize, WSM_TOT);

    prep_kernel<<<(NP * KP + 255) / 256, 256>>>(W_ih, W_hh, b_ih, b_hh, W1);
    assemble_kernel<<<BATCH / 8, 256>>>(n_id, memory, last_update, store_src,
                                        store_dst, store_t, store_msg, time_w, time_b);
    gemm_kernel<<<dim3(5, BATCH / BMM), 256, SMEM_TOT>>>();
    w1bn_kernel<<<BATCH / 128, 256, WSM_TOT>>>(b1);
    finalize_kernel<<<1, 64>>>(gamma, beta, W2, b2);
    out_kernel<<<BATCH / 256, 256>>>(out);
}

// round 13
// speedup vs baseline: 1.0372x; 1.0372x over previous
#include <cuda_runtime.h>
#include <cuda_fp16.h>
#include <math.h>
#include <stdint.h>

#define BATCH   262144
#define DD      100
#define KP      416       // padded K (fp16 cols): 404 -> 416 (last chunk = 32 real cols)
#define NP      400       // interleaved gate rows: 100 quadruples (r,z,n,hn)
#define BMM     128
#define BNN     80
#define NCHUNK  7         // 6 full 64-col chunks + 1 half (32-col) chunk
#define XLP     104       // packed X_lo width (h cols only)

// -------- device scratch --------
__device__ __half g_Xhi[(size_t)BATCH * KP];
__device__ __half g_Xlo[(size_t)BATCH * XLP];  // packed: cols 304..403 of X (for exact h)
__device__ __half g_Whi[(size_t)NP * KP];
__device__ __half g_W1h[64 * 128];             // W1 fp16, K padded to 128
__device__ float g_bq[NP];
__device__ __half g_HNh[(size_t)BATCH * 128];  // h_new fp16, 128-col padded
__device__ __half g_Ah[(size_t)BATCH * 64];    // relu(...) fp16
__device__ float g_stats[128];
__device__ float g_W2e[128];
__device__ float g_be[2];

__device__ __forceinline__ uint32_t smem_u32(const void* p) {
    uint32_t a;
    asm("{ .reg .u64 t; cvta.to.shared.u64 t, %1; cvt.u32.u64 %0, t; }" : "=r"(a) : "l"(p));
    return a;
}
#define LDSM4(r, a) asm volatile("ldmatrix.sync.aligned.m8n8.x4.shared.b16 {%0,%1,%2,%3}, [%4];" \
    : "=r"((r)[0]), "=r"((r)[1]), "=r"((r)[2]), "=r"((r)[3]) : "r"(a))
#define LDSM2(r, a) asm volatile("ldmatrix.sync.aligned.m8n8.x2.shared.b16 {%0,%1}, [%2];" \
    : "=r"((r)[0]), "=r"((r)[1]) : "r"(a))
#define MMA(c, a, b) asm volatile( \
    "mma.sync.aligned.m16n8k16.row.col.f32.f16.f16.f32 {%0,%1,%2,%3},{%4,%5,%6,%7},{%8,%9},{%0,%1,%2,%3};" \
    : "+f"((c)[0]), "+f"((c)[1]), "+f"((c)[2]), "+f"((c)[3])                                                \
    : "r"((a)[0]), "r"((a)[1]), "r"((a)[2]), "r"((a)[3]), "r"((b)[0]), "r"((b)[1]))
__device__ __forceinline__ void cpa16(uint32_t d, const void* s) {
    asm volatile("{ .reg .u64 g; cvta.to.global.u64 g, %1; cp.async.cg.shared.global [%0], [g], 16; }"
                 :: "r"(d), "l"(s));
}
#define CPA_COMMIT() asm volatile("cp.async.commit_group;" ::: "memory")

// fast accurate cos: Cody-Waite reduction (|arg| < ~1e5) + __cosf on [-pi,pi]
__device__ __forceinline__ float fast_cos(float a) {
    float k = rintf(a * 0.15915494309189535f);
    float r = fmaf(k, -6.2831854820251465f, a);   // 2pi hi (exact fma)
    r = fmaf(k, 1.7484555e-7f, r);                // -(2pi - hi)
    return __cosf(r);
}

// gemm smem: 3 stages of 26KB, then bias
#define STAGE_SZ 26624
#define SBIAS    79872
#define SMEM_TOT 80256
// w1bn smem
#define WSM_B1   49152
#define WSM_S    49408
#define WSM_Q    49664
#define WSM_TOT  49920

// ===================== K0: prep interleaved weights (fp16) =====================
__global__ __launch_bounds__(256) void prep_kernel(const float* __restrict__ W_ih,
                                                   const float* __restrict__ W_hh,
                                                   const float* __restrict__ b_ih,
                                                   const float* __restrict__ b_hh,
                                                   const float* __restrict__ W1) {
    int idx = blockIdx.x * 256 + threadIdx.x;
    if (idx < NP * KP) {
        int r = idx / KP, k = idx % KP;
        int d = r >> 2, g = r & 3;
        float v = 0.f;
        if (g == 0) {
            if (k < 304)      v = W_ih[d * 304 + k];
            else if (k < 404) v = W_hh[d * 100 + (k - 304)];
        } else if (g == 1) {
            int rr = 100 + d;
            if (k < 304)      v = W_ih[rr * 304 + k];
            else if (k < 404) v = W_hh[rr * 100 + (k - 304)];
        } else if (g == 2) {
            if (k < 304)      v = W_ih[(200 + d) * 304 + k];
        } else {
            if (k >= 304 && k < 404) v = W_hh[(200 + d) * 100 + (k - 304)];
        }
        g_Whi[idx] = __float2half(v);
    }
    if (idx < 64 * 128) {
        int n = idx >> 7, k = idx & 127;
        g_W1h[idx] = __float2half(k < 100 ? W1[n * 100 + k] : 0.f);
    }
    if (idx < NP) {
        int d = idx >> 2, g = idx & 3;
        float bv;
        if (g == 0)      bv = b_ih[d] + b_hh[d];
        else if (g == 1) bv = b_ih[100 + d] + b_hh[100 + d];
        else if (g == 2) bv = b_ih[200 + d];
        else             bv = b_hh[200 + d];
        g_bq[idx] = bv;
    }
    if (idx < 128) g_stats[idx] = 0.f;
}

// ===================== K1: gather + assemble X (vectorized, fast cos) ==========
__global__ __launch_bounds__(256) void assemble_kernel(const int*   __restrict__ n_id,
                                                       const float* __restrict__ memory,
                                                       const int*   __restrict__ last_update,
                                                       const int*   __restrict__ store_src,
                                                       const int*   __restrict__ store_dst,
                                                       const int*   __restrict__ store_t,
                                                       const float* __restrict__ store_msg,
                                                       const float* __restrict__ time_w,
                                                       const float* __restrict__ time_b) {
    int w = threadIdx.x >> 5, lane = threadIdx.x & 31;
    int b = blockIdx.x * 8 + w;
    int n   = n_id[b];
    int src = store_src[n];
    int dst = store_dst[n];
    float dt = (float)(store_t[n] - last_update[n]);
    const float2* ms2 = (const float2*)(memory + (size_t)src * DD);   // 8B aligned
    const float2* md2 = (const float2*)(memory + (size_t)dst * DD);
    const float2* mn2 = (const float2*)(memory + (size_t)n   * DD);
    const float2* mg2 = (const float2*)(store_msg + (size_t)n * 4);
    const float2* tw2 = (const float2*)time_w;
    const float2* tb2 = (const float2*)time_b;
    __half2* xh2 = (__half2*)(g_Xhi + (size_t)b * KP);
    __half2* xl2 = (__half2*)(g_Xlo + (size_t)b * XLP);
    // 208 half2 cols: [0,50) ms | [50,100) md | [100,102) msg | [102,152) tenc
    //                 | [152,202) h=mn | [202,208) zero
    #pragma unroll
    for (int it = 0; it < 7; it++) {
        int c2 = it * 32 + lane;
        if (c2 >= 208) break;
        float2 v;
        bool is_h = false;
        if (c2 < 50)        v = ms2[c2];
        else if (c2 < 100)  v = md2[c2 - 50];
        else if (c2 < 102)  v = mg2[c2 - 100];
        else if (c2 < 152) {
            int j = c2 - 102;
            float2 tw = tw2[j], tb = tb2[j];
            float a0 = __fadd_rn(__fmul_rn(dt, tw.x), tb.x);  // no fma (match jax)
            float a1 = __fadd_rn(__fmul_rn(dt, tw.y), tb.y);
            v.x = fast_cos(a0);
            v.y = fast_cos(a1);
        }
        else if (c2 < 202) { v = mn2[c2 - 152]; is_h = true; }
        else                v = make_float2(0.f, 0.f);
        __half2 h2 = __floats2half2_rn(v.x, v.y);
        xh2[c2] = h2;
        if (is_h) {
            float2 back = __half22float2(h2);
            xl2[c2 - 152] = __floats2half2_rn(v.x - back.x, v.y - back.y);
        }
    }
}

// ===================== K2: HMMA GEMM (fp16, 3-stage, single-sync) + GRU ====
__global__ __launch_bounds__(256, 2) void gemm_kernel() {
    extern __shared__ char sm[];
    const uint32_t sb = smem_u32(sm);
    const int tid = threadIdx.x, wid = tid >> 5, lane = tid & 31;
    const int nt = blockIdx.x;            // N-tile fastest -> A reuse in L2
    const int m0 = blockIdx.y * BMM;
    const int n0 = nt * BNN;
    const int wm0 = (wid & 3) * 32;
    const int wn0 = (wid >> 2) * 40;

    if (tid < BNN) ((float*)(sm + SBIAS))[tid] = g_bq[n0 + tid];

    float c[2][5][4];
    #pragma unroll
    for (int i = 0; i < 2; i++)
        #pragma unroll
        for (int j = 0; j < 5; j++)
            #pragma unroll
            for (int q = 0; q < 4; q++) c[i][j][q] = 0.f;

    auto stage = [&](int ch, uint32_t base) {
        #pragma unroll 1
        for (int i = tid; i < 1664; i += 256) {
            int j = i & 7;
            if (ch == 6 && j >= 4) continue;   // cols 416+ don't exist
            uint32_t dst;
            const char* src;
            if (i < 1024) {
                int r = i >> 3;
                src = (const char*)g_Xhi + (size_t)(m0 + r) * (KP * 2) + ch * 128 + j * 16;
                dst = base + r * 128 + ((j ^ (r & 7)) << 4);
            } else {
                int r = (i - 1024) >> 3;
                src = (const char*)g_Whi + (size_t)(n0 + r) * (KP * 2) + ch * 128 + j * 16;
                dst = base + 16384 + r * 128 + ((j ^ (r & 7)) << 4);
            }
            cpa16(dst, src);
        }
        CPA_COMMIT();
    };

    stage(0, sb);
    stage(1, sb + STAGE_SZ);

    uint32_t stoff[3] = {0u, STAGE_SZ, 2u * STAGE_SZ};

    for (int ch = 0; ch < NCHUNK; ch++) {
        if (ch < NCHUNK - 1) asm volatile("cp.async.wait_group 1;" ::: "memory");
        else                 asm volatile("cp.async.wait_group 0;" ::: "memory");
        __syncthreads();
        if (ch + 2 < NCHUNK) stage(ch + 2, sb + stoff[(ch + 2) % 3]);  // overlaps compute(ch)
        const uint32_t st = sb + stoff[ch % 3];
        const int nks = (ch == NCHUNK - 1) ? 2 : 4;
        for (int ks = 0; ks < nks; ks++) {
            uint32_t ah[2][4], bh[5][2];
            int arow = wm0 + (lane & 7) + ((lane >> 3) & 1) * 8;
            int achk = 2 * ks + (lane >> 4);
            #pragma unroll
            for (int i = 0; i < 2; i++) {
                int r = arow + i * 16;
                LDSM4(ah[i], st + r * 128 + ((achk ^ (r & 7)) << 4));
            }
            {
                int rr = wn0 + (lane & 7);
                int chk2 = 2 * ks + ((lane >> 3) & 1);
                #pragma unroll
                for (int jp = 0; jp < 2; jp++) {
                    int r = rr + (jp * 2 + (lane >> 4)) * 8;
                    uint32_t off = r * 128 + ((chk2 ^ (r & 7)) << 4);
                    uint32_t t4[4];
                    LDSM4(t4, st + 16384 + off);
                    bh[jp*2][0]   = t4[0]; bh[jp*2][1]   = t4[1];
                    bh[jp*2+1][0] = t4[2]; bh[jp*2+1][1] = t4[3];
                }
                int r = rr + 32;
                uint32_t off = r * 128 + ((chk2 ^ (r & 7)) << 4);
                LDSM2(bh[4], st + 16384 + off);
            }
            #pragma unroll
            for (int i = 0; i < 2; i++)
                #pragma unroll
                for (int j = 0; j < 5; j++)
                    MMA(c[i][j], ah[i], bh[j]);
        }
    }
    __syncthreads();   // last compute done before smem reuse for C staging

    // stage C (+bias) into smem: 128 x 84 floats
    float* Cs = (float*)sm;
    const float* sbias = (const float*)(sm + SBIAS);
    #pragma unroll
    for (int i = 0; i < 2; i++) {
        int r0 = wm0 + i * 16 + (lane >> 2);
        #pragma unroll
        for (int j = 0; j < 5; j++) {
            int cc = wn0 + j * 8 + 2 * (lane & 3);
            float bz0 = sbias[cc], bz1 = sbias[cc + 1];
            Cs[r0 * 84 + cc]           = c[i][j][0] + bz0;
            Cs[r0 * 84 + cc + 1]       = c[i][j][1] + bz1;
            Cs[(r0 + 8) * 84 + cc]     = c[i][j][2] + bz0;
            Cs[(r0 + 8) * 84 + cc + 1] = c[i][j][3] + bz1;
        }
    }
    __syncthreads();

    // fused GRU epilogue: 128 rows x 20 quadruples -> fp16 h_new
    for (int g = tid; g < 128 * 20; g += 256) {
        int m = g / 20, dl = g % 20;
        float4 v = *(const float4*)&Cs[m * 84 + 4 * dl];
        int dg = nt * 20 + dl;
        int mg = m0 + m;
        float h = __half2float(g_Xhi[(size_t)mg * KP + 304 + dg]) +
                  __half2float(g_Xlo[(size_t)mg * XLP + dg]);
        float rr = 1.f / (1.f + __expf(-v.x));
        float zz = 1.f / (1.f + __expf(-v.y));
        float nn = tanhf(v.z + rr * v.w);
        g_HNh[(size_t)mg * 128 + dg] = __float2half((1.f - zz) * nn + zz * h);
    }
}

// ===================== K3: HMMA A = relu(HN @ W1^T + b1) + BN stats =============
__global__ __launch_bounds__(256) void w1bn_kernel(const float* __restrict__ b1) {
    extern __shared__ char wsm[];
    const uint32_t sb = smem_u32(wsm);
    const int tid = threadIdx.x, wid = tid >> 5, lane = tid & 31;
    const int m0 = blockIdx.x * 128;
    const int wm0 = (wid & 3) * 32;
    const int wn0 = (wid >> 2) * 32;
    float* b1s  = (float*)(wsm + WSM_B1);
    float* sacc = (float*)(wsm + WSM_S);
    float* qacc = (float*)(wsm + WSM_Q);
    if (tid < 64) { b1s[tid] = b1[tid]; sacc[tid] = 0.f; qacc[tid] = 0.f; }

    #pragma unroll 1
    for (int i = tid; i < 3072; i += 256) {
        uint32_t dst;
        const char* src;
        if (i < 2048) {
            int ch = i >> 10, ii = i & 1023, r = ii >> 3, j = ii & 7;
            src = (const char*)g_HNh + (size_t)(m0 + r) * 256 + ch * 128 + j * 16;
            dst = sb + ch * 16384 + r * 128 + ((j ^ (r & 7)) << 4);
        } else {
            int ii = i - 2048;
            int ch = ii >> 9, i2 = ii & 511, r = i2 >> 3, j = i2 & 7;
            src = (const char*)g_W1h + (size_t)r * 256 + ch * 128 + j * 16;
            dst = sb + 32768 + ch * 8192 + r * 128 + ((j ^ (r & 7)) << 4);
        }
        cpa16(dst, src);
    }
    CPA_COMMIT();
    asm volatile("cp.async.wait_group 0;" ::: "memory");
    __syncthreads();

    float c[2][4][4];
    #pragma unroll
    for (int i = 0; i < 2; i++)
        #pragma unroll
        for (int j = 0; j < 4; j++)
            #pragma unroll
            for (int q = 0; q < 4; q++) c[i][j][q] = 0.f;

    #pragma unroll
    for (int ks = 0; ks < 8; ks++) {
        int ch = ks >> 2, kk = ks & 3;
        uint32_t ah[2][4], bh[4][2];
        int arow = wm0 + (lane & 7) + ((lane >> 3) & 1) * 8;
        int achk = 2 * kk + (lane >> 4);
        #pragma unroll
        for (int i = 0; i < 2; i++) {
            int r = arow + i * 16;
            LDSM4(ah[i], sb + ch * 16384 + r * 128 + ((achk ^ (r & 7)) << 4));
        }
        int rr = wn0 + (lane & 7);
        int chk2 = 2 * kk + ((lane >> 3) & 1);
        #pragma unroll
        for (int jp = 0; jp < 2; jp++) {
            int r = rr + (jp * 2 + (lane >> 4)) * 8;
            uint32_t off = r * 128 + ((chk2 ^ (r & 7)) << 4);
            uint32_t t4[4];
            LDSM4(t4, sb + 32768 + ch * 8192 + off);
            bh[jp*2][0]   = t4[0]; bh[jp*2][1]   = t4[1];
            bh[jp*2+1][0] = t4[2]; bh[jp*2+1][1] = t4[3];
        }
        #pragma unroll
        for (int i = 0; i < 2; i++)
            #pragma unroll
            for (int j = 0; j < 4; j++)
                MMA(c[i][j], ah[i], bh[j]);
    }

    #pragma unroll
    for (int j = 0; j < 4; j++) {
        int col = wn0 + j * 8 + 2 * (lane & 3);
        float bz0 = b1s[col], bz1 = b1s[col + 1];
        float s0 = 0.f, q0 = 0.f, s1 = 0.f, q1 = 0.f;
        #pragma unroll
        for (int i = 0; i < 2; i++) {
            int row = m0 + wm0 + i * 16 + (lane >> 2);
            float a0 = fmaxf(c[i][j][0] + bz0, 0.f);
            float a1 = fmaxf(c[i][j][1] + bz1, 0.f);
            float a2 = fmaxf(c[i][j][2] + bz0, 0.f);
            float a3 = fmaxf(c[i][j][3] + bz1, 0.f);
            *(__half2*)&g_Ah[(size_t)row * 64 + col]       = __floats2half2_rn(a0, a1);
            *(__half2*)&g_Ah[(size_t)(row + 8) * 64 + col] = __floats2half2_rn(a2, a3);
            s0 += a0 + a2; q0 += a0 * a0 + a2 * a2;
            s1 += a1 + a3; q1 += a1 * a1 + a3 * a3;
        }
        #pragma unroll
        for (int off = 4; off <= 16; off <<= 1) {
            s0 += __shfl_xor_sync(0xffffffff, s0, off);
            q0 += __shfl_xor_sync(0xffffffff, q0, off);
            s1 += __shfl_xor_sync(0xffffffff, s1, off);
            q1 += __shfl_xor_sync(0xffffffff, q1, off);
        }
        if (lane < 4) {
            atomicAdd(&sacc[col], s0); atomicAdd(&qacc[col], q0);
            atomicAdd(&sacc[col + 1], s1); atomicAdd(&qacc[col + 1], q1);
        }
    }
    __syncthreads();
    if (tid < 64) {
        atomicAdd(&g_stats[tid],      sacc[tid]);
        atomicAdd(&g_stats[64 + tid], qacc[tid]);
    }
}

// ===================== K4: finalize BN, fold into W2 =====================
__global__ void finalize_kernel(const float* __restrict__ gamma,
                                const float* __restrict__ beta,
                                const float* __restrict__ W2,
                                const float* __restrict__ b2) {
    __shared__ float red0[64], red1[64];
    int j = threadIdx.x;
    float mu  = g_stats[j]      * (1.f / BATCH);
    float var = g_stats[64 + j] * (1.f / BATCH) - mu * mu;
    float inv = rsqrtf(var + 1e-5f);
    float gsc = gamma[j] * inv;
    float w0 = W2[j], w1 = W2[64 + j];
    g_W2e[2 * j]     = w0 * gsc;
    g_W2e[2 * j + 1] = w1 * gsc;
    float c = beta[j] - mu * gsc;
    red0[j] = c * w0;
    red1[j] = c * w1;
    __syncthreads();
    if (j == 0) { float s = 0.f; for (int i = 0; i < 64; i++) s += red0[i]; g_be[0] = b2[0] + s; }
    if (j == 1) { float s = 0.f; for (int i = 0; i < 64; i++) s += red1[i]; g_be[1] = b2[1] + s; }
}

// ===================== K5: output = A @ W2e + be =====================
__global__ __launch_bounds__(256) void out_kernel(float* __restrict__ out) {
    __shared__ float w2s[128];
    __shared__ float bes[2];
    int tid = threadIdx.x;
    if (tid < 128) w2s[tid] = g_W2e[tid];
    if (tid < 2)   bes[tid] = g_be[tid];
    __syncthreads();
    int b = blockIdx.x * 256 + tid;
    const __half2* ar = (const __half2*)(g_Ah + (size_t)b * 64);
    float o0 = bes[0], o1 = bes[1];
    #pragma unroll
    for (int q = 0; q < 32; q++) {
        float2 v = __half22float2(ar[q]);
        o0 += v.x * w2s[4 * q]     + v.y * w2s[4 * q + 2];
        o1 += v.x * w2s[4 * q + 1] + v.y * w2s[4 * q + 3];
    }
    ((float2*)out)[b] = make_float2(o0, o1);
}

// ===================== launcher =====================
extern "C" void kernel_launch(void* const* d_in, const int* in_sizes, int n_in,
                              void* d_out, int out_size) {
    const int*   n_id        = (const int*)  d_in[0];
    const float* memory      = (const float*)d_in[1];
    const int*   last_update = (const int*)  d_in[2];
    const int*   store_src   = (const int*)  d_in[3];
    const int*   store_dst   = (const int*)  d_in[4];
    const int*   store_t     = (const int*)  d_in[5];
    const float* store_msg   = (const float*)d_in[6];
    const float* time_w      = (const float*)d_in[7];
    const float* time_b      = (const float*)d_in[8];
    const float* W_ih        = (const float*)d_in[9];
    const float* b_ih        = (const float*)d_in[10];
    const float* W_hh        = (const float*)d_in[11];
    const float* b_hh        = (const float*)d_in[12];
    const float* W1          = (const float*)d_in[13];
    const float* b1          = (const float*)d_in[14];
    const float* gamma       = (const float*)d_in[15];
    const float* beta        = (const float*)d_in[16];
    const float* W2          = (const float*)d_in[17];
    const float* b2          = (const float*)d_in[18];
    float*       out         = (float*)d_out;

    cudaFuncSetAttribute(gemm_kernel, cudaFuncAttributeMaxDynamicSharedMemorySize, SMEM_TOT);
    cudaFuncSetAttribute(w1bn_kernel, cudaFuncAttributeMaxDynamicSharedMemorySize, WSM_TOT);

    prep_kernel<<<(NP * KP + 255) / 256, 256>>>(W_ih, W_hh, b_ih, b_hh, W1);
    assemble_kernel<<<BATCH / 8, 256>>>(n_id, memory, last_update, store_src,
                                        store_dst, store_t, store_msg, time_w, time_b);
    gemm_kernel<<<dim3(5, BATCH / BMM), 256, SMEM_TOT>>>();
    w1bn_kernel<<<BATCH / 128, 256, WSM_TOT>>>(b1);
    finalize_kernel<<<1, 64>>>(gamma, beta, W2, b2);
    out_kernel<<<BATCH / 256, 256>>>(out);
}

// round 14
// speedup vs baseline: 1.4534x; 1.4013x over previous
#include <cuda_runtime.h>
#include <cuda_fp16.h>
#include <math.h>
#include <stdint.h>

#define BATCH   262144
#define DD      100
#define KP      416       // padded K (fp16 cols): 404 -> 416 (last chunk = 32 real cols)
#define NP      400       // interleaved gate rows: 100 quadruples (r,z,n,hn)
#define BMM     128
#define BNN     80
#define NCHUNK  7         // 6 full 64-col chunks + 1 half (32-col) chunk
#define XLP     104       // packed X_lo width (h cols only)

// -------- device scratch --------
__device__ __half g_Xhi[(size_t)BATCH * KP];
__device__ __half g_Xlo[(size_t)BATCH * XLP];  // packed: cols 304..403 of X (for exact h)
__device__ __half g_Whi[(size_t)NP * KP];
__device__ __half g_W1h[64 * 128];             // W1 fp16, K padded to 128
__device__ float g_bq[NP];
__device__ __half g_HNh[(size_t)BATCH * 128];  // h_new fp16, 128-col padded
__device__ __half g_Ah[(size_t)BATCH * 64];    // relu(...) fp16
__device__ float g_stats[128];
__device__ float g_W2e[128];
__device__ float g_be[2];

__device__ __forceinline__ uint32_t smem_u32(const void* p) {
    uint32_t a;
    asm("{ .reg .u64 t; cvta.to.shared.u64 t, %1; cvt.u32.u64 %0, t; }" : "=r"(a) : "l"(p));
    return a;
}
#define LDSM4(r, a) asm volatile("ldmatrix.sync.aligned.m8n8.x4.shared.b16 {%0,%1,%2,%3}, [%4];" \
    : "=r"((r)[0]), "=r"((r)[1]), "=r"((r)[2]), "=r"((r)[3]) : "r"(a))
#define LDSM2(r, a) asm volatile("ldmatrix.sync.aligned.m8n8.x2.shared.b16 {%0,%1}, [%2];" \
    : "=r"((r)[0]), "=r"((r)[1]) : "r"(a))
#define MMA(c, a, b) asm volatile( \
    "mma.sync.aligned.m16n8k16.row.col.f32.f16.f16.f32 {%0,%1,%2,%3},{%4,%5,%6,%7},{%8,%9},{%0,%1,%2,%3};" \
    : "+f"((c)[0]), "+f"((c)[1]), "+f"((c)[2]), "+f"((c)[3])                                                \
    : "r"((a)[0]), "r"((a)[1]), "r"((a)[2]), "r"((a)[3]), "r"((b)[0]), "r"((b)[1]))
__device__ __forceinline__ void cpa16(uint32_t d, const void* s) {
    asm volatile("{ .reg .u64 g; cvta.to.global.u64 g, %1; cp.async.cg.shared.global [%0], [g], 16; }"
                 :: "r"(d), "l"(s));
}
#define CPA_COMMIT() asm volatile("cp.async.commit_group;" ::: "memory")

// fast accurate cos: Cody-Waite reduction (|arg| < ~1e5) + __cosf on [-pi,pi]
__device__ __forceinline__ float fast_cos(float a) {
    float k = rintf(a * 0.15915494309189535f);
    float r = fmaf(k, -6.2831854820251465f, a);   // 2pi hi (exact fma)
    r = fmaf(k, 1.7484555e-7f, r);                // -(2pi - hi)
    return __cosf(r);
}

// gemm smem: 3 stages of 26KB, then bias
#define STAGE_SZ 26624
#define SBIAS    79872
#define SMEM_TOT 80256
// w1bn smem
#define WSM_B1   49152
#define WSM_S    49408
#define WSM_Q    49664
#define WSM_TOT  49920

// ===================== K0: prep interleaved weights (fp16) =====================
__global__ __launch_bounds__(256) void prep_kernel(const float* __restrict__ W_ih,
                                                   const float* __restrict__ W_hh,
                                                   const float* __restrict__ b_ih,
                                                   const float* __restrict__ b_hh,
                                                   const float* __restrict__ W1) {
    int idx = blockIdx.x * 256 + threadIdx.x;
    if (idx < NP * KP) {
        int r = idx / KP, k = idx % KP;
        int d = r >> 2, g = r & 3;
        float v = 0.f;
        if (g == 0) {
            if (k < 304)      v = W_ih[d * 304 + k];
            else if (k < 404) v = W_hh[d * 100 + (k - 304)];
        } else if (g == 1) {
            int rr = 100 + d;
            if (k < 304)      v = W_ih[rr * 304 + k];
            else if (k < 404) v = W_hh[rr * 100 + (k - 304)];
        } else if (g == 2) {
            if (k < 304)      v = W_ih[(200 + d) * 304 + k];
        } else {
            if (k >= 304 && k < 404) v = W_hh[(200 + d) * 100 + (k - 304)];
        }
        g_Whi[idx] = __float2half(v);
    }
    if (idx < 64 * 128) {
        int n = idx >> 7, k = idx & 127;
        g_W1h[idx] = __float2half(k < 100 ? W1[n * 100 + k] : 0.f);
    }
    if (idx < NP) {
        int d = idx >> 2, g = idx & 3;
        float bv;
        if (g == 0)      bv = b_ih[d] + b_hh[d];
        else if (g == 1) bv = b_ih[100 + d] + b_hh[100 + d];
        else if (g == 2) bv = b_ih[200 + d];
        else             bv = b_hh[200 + d];
        g_bq[idx] = bv;
    }
    if (idx < 128) g_stats[idx] = 0.f;
}

// ===================== K1: gather + assemble X (R11 scalar structure + fast_cos)
__global__ __launch_bounds__(256) void assemble_kernel(const int*   __restrict__ n_id,
                                                       const float* __restrict__ memory,
                                                       const int*   __restrict__ last_update,
                                                       const int*   __restrict__ store_src,
                                                       const int*   __restrict__ store_dst,
                                                       const int*   __restrict__ store_t,
                                                       const float* __restrict__ store_msg,
                                                       const float* __restrict__ time_w,
                                                       const float* __restrict__ time_b) {
    int w = threadIdx.x >> 5, lane = threadIdx.x & 31;
    int b = blockIdx.x * 8 + w;
    int n   = n_id[b];
    int src = store_src[n];
    int dst = store_dst[n];
    float dt = (float)(store_t[n] - last_update[n]);
    const float* ms = memory + (size_t)src * DD;
    const float* md = memory + (size_t)dst * DD;
    const float* mn = memory + (size_t)n   * DD;
    __half* xh = g_Xhi + (size_t)b * KP;
    __half* xl = g_Xlo + (size_t)b * XLP;
    #pragma unroll
    for (int c = lane; c < KP; c += 32) {
        float v;
        if (c < 100)      v = ms[c];
        else if (c < 200) v = md[c - 100];
        else if (c < 204) v = store_msg[(size_t)n * 4 + (c - 200)];
        else if (c < 304) {
            int j = c - 204;
            float arg = __fadd_rn(__fmul_rn(dt, time_w[j]), time_b[j]);  // no fma (match jax)
            v = fast_cos(arg);
        }
        else if (c < 404) v = mn[c - 304];
        else              v = 0.f;
        __half hi = __float2half(v);
        xh[c] = hi;
        if (c >= 304 && c < 404)
            xl[c - 304] = __float2half(v - __half2float(hi));
    }
}

// ===================== K2: HMMA GEMM (fp16, 3-stage, single-sync) + GRU ====
__global__ __launch_bounds__(256, 2) void gemm_kernel() {
    extern __shared__ char sm[];
    const uint32_t sb = smem_u32(sm);
    const int tid = threadIdx.x, wid = tid >> 5, lane = tid & 31;
    const int nt = blockIdx.x;            // N-tile fastest -> A reuse in L2
    const int m0 = blockIdx.y * BMM;
    const int n0 = nt * BNN;
    const int wm0 = (wid & 3) * 32;
    const int wn0 = (wid >> 2) * 40;

    if (tid < BNN) ((float*)(sm + SBIAS))[tid] = g_bq[n0 + tid];

    float c[2][5][4];
    #pragma unroll
    for (int i = 0; i < 2; i++)
        #pragma unroll
        for (int j = 0; j < 5; j++)
            #pragma unroll
            for (int q = 0; q < 4; q++) c[i][j][q] = 0.f;

    auto stage = [&](int ch, uint32_t base) {
        #pragma unroll 1
        for (int i = tid; i < 1664; i += 256) {
            int j = i & 7;
            if (ch == 6 && j >= 4) continue;   // cols 416+ don't exist
            uint32_t dst;
            const char* src;
            if (i < 1024) {
                int r = i >> 3;
                src = (const char*)g_Xhi + (size_t)(m0 + r) * (KP * 2) + ch * 128 + j * 16;
                dst = base + r * 128 + ((j ^ (r & 7)) << 4);
            } else {
                int r = (i - 1024) >> 3;
                src = (const char*)g_Whi + (size_t)(n0 + r) * (KP * 2) + ch * 128 + j * 16;
                dst = base + 16384 + r * 128 + ((j ^ (r & 7)) << 4);
            }
            cpa16(dst, src);
        }
        CPA_COMMIT();
    };

    stage(0, sb);
    stage(1, sb + STAGE_SZ);

    uint32_t stoff[3] = {0u, STAGE_SZ, 2u * STAGE_SZ};

    for (int ch = 0; ch < NCHUNK; ch++) {
        if (ch < NCHUNK - 1) asm volatile("cp.async.wait_group 1;" ::: "memory");
        else                 asm volatile("cp.async.wait_group 0;" ::: "memory");
        __syncthreads();
        if (ch + 2 < NCHUNK) stage(ch + 2, sb + stoff[(ch + 2) % 3]);  // overlaps compute(ch)
        const uint32_t st = sb + stoff[ch % 3];
        const int nks = (ch == NCHUNK - 1) ? 2 : 4;
        for (int ks = 0; ks < nks; ks++) {
            uint32_t ah[2][4], bh[5][2];
            int arow = wm0 + (lane & 7) + ((lane >> 3) & 1) * 8;
            int achk = 2 * ks + (lane >> 4);
            #pragma unroll
            for (int i = 0; i < 2; i++) {
                int r = arow + i * 16;
                LDSM4(ah[i], st + r * 128 + ((achk ^ (r & 7)) << 4));
            }
            {
                int rr = wn0 + (lane & 7);
                int chk2 = 2 * ks + ((lane >> 3) & 1);
                #pragma unroll
                for (int jp = 0; jp < 2; jp++) {
                    int r = rr + (jp * 2 + (lane >> 4)) * 8;
                    uint32_t off = r * 128 + ((chk2 ^ (r & 7)) << 4);
                    uint32_t t4[4];
                    LDSM4(t4, st + 16384 + off);
                    bh[jp*2][0]   = t4[0]; bh[jp*2][1]   = t4[1];
                    bh[jp*2+1][0] = t4[2]; bh[jp*2+1][1] = t4[3];
                }
                int r = rr + 32;
                uint32_t off = r * 128 + ((chk2 ^ (r & 7)) << 4);
                LDSM2(bh[4], st + 16384 + off);
            }
            #pragma unroll
            for (int i = 0; i < 2; i++)
                #pragma unroll
                for (int j = 0; j < 5; j++)
                    MMA(c[i][j], ah[i], bh[j]);
        }
    }
    __syncthreads();   // last compute done before smem reuse for C staging

    // stage C (+bias) into smem: 128 x 84 floats
    float* Cs = (float*)sm;
    const float* sbias = (const float*)(sm + SBIAS);
    #pragma unroll
    for (int i = 0; i < 2; i++) {
        int r0 = wm0 + i * 16 + (lane >> 2);
        #pragma unroll
        for (int j = 0; j < 5; j++) {
            int cc = wn0 + j * 8 + 2 * (lane & 3);
            float bz0 = sbias[cc], bz1 = sbias[cc + 1];
            Cs[r0 * 84 + cc]           = c[i][j][0] + bz0;
            Cs[r0 * 84 + cc + 1]       = c[i][j][1] + bz1;
            Cs[(r0 + 8) * 84 + cc]     = c[i][j][2] + bz0;
            Cs[(r0 + 8) * 84 + cc + 1] = c[i][j][3] + bz1;
        }
    }
    __syncthreads();

    // fused GRU epilogue: 128 rows x 20 quadruples -> fp16 h_new
    for (int g = tid; g < 128 * 20; g += 256) {
        int m = g / 20, dl = g % 20;
        float4 v = *(const float4*)&Cs[m * 84 + 4 * dl];
        int dg = nt * 20 + dl;
        int mg = m0 + m;
        float h = __half2float(g_Xhi[(size_t)mg * KP + 304 + dg]) +
                  __half2float(g_Xlo[(size_t)mg * XLP + dg]);
        float rr = 1.f / (1.f + __expf(-v.x));
        float zz = 1.f / (1.f + __expf(-v.y));
        float nn = tanhf(v.z + rr * v.w);
        g_HNh[(size_t)mg * 128 + dg] = __float2half((1.f - zz) * nn + zz * h);
    }
}

// ===================== K3: HMMA A = relu(HN @ W1^T + b1) + BN stats =============
__global__ __launch_bounds__(256) void w1bn_kernel(const float* __restrict__ b1) {
    extern __shared__ char wsm[];
    const uint32_t sb = smem_u32(wsm);
    const int tid = threadIdx.x, wid = tid >> 5, lane = tid & 31;
    const int m0 = blockIdx.x * 128;
    const int wm0 = (wid & 3) * 32;
    const int wn0 = (wid >> 2) * 32;
    float* b1s  = (float*)(wsm + WSM_B1);
    float* sacc = (float*)(wsm + WSM_S);
    float* qacc = (float*)(wsm + WSM_Q);
    if (tid < 64) { b1s[tid] = b1[tid]; sacc[tid] = 0.f; qacc[tid] = 0.f; }

    #pragma unroll 1
    for (int i = tid; i < 3072; i += 256) {
        uint32_t dst;
        const char* src;
        if (i < 2048) {
            int ch = i >> 10, ii = i & 1023, r = ii >> 3, j = ii & 7;
            src = (const char*)g_HNh + (size_t)(m0 + r) * 256 + ch * 128 + j * 16;
            dst = sb + ch * 16384 + r * 128 + ((j ^ (r & 7)) << 4);
        } else {
            int ii = i - 2048;
            int ch = ii >> 9, i2 = ii & 511, r = i2 >> 3, j = i2 & 7;
            src = (const char*)g_W1h + (size_t)r * 256 + ch * 128 + j * 16;
            dst = sb + 32768 + ch * 8192 + r * 128 + ((j ^ (r & 7)) << 4);
        }
        cpa16(dst, src);
    }
    CPA_COMMIT();
    asm volatile("cp.async.wait_group 0;" ::: "memory");
    __syncthreads();

    float c[2][4][4];
    #pragma unroll
    for (int i = 0; i < 2; i++)
        #pragma unroll
        for (int j = 0; j < 4; j++)
            #pragma unroll
            for (int q = 0; q < 4; q++) c[i][j][q] = 0.f;

    #pragma unroll
    for (int ks = 0; ks < 8; ks++) {
        int ch = ks >> 2, kk = ks & 3;
        uint32_t ah[2][4], bh[4][2];
        int arow = wm0 + (lane & 7) + ((lane >> 3) & 1) * 8;
        int achk = 2 * kk + (lane >> 4);
        #pragma unroll
        for (int i = 0; i < 2; i++) {
            int r = arow + i * 16;
            LDSM4(ah[i], sb + ch * 16384 + r * 128 + ((achk ^ (r & 7)) << 4));
        }
        int rr = wn0 + (lane & 7);
        int chk2 = 2 * kk + ((lane >> 3) & 1);
        #pragma unroll
        for (int jp = 0; jp < 2; jp++) {
            int r = rr + (jp * 2 + (lane >> 4)) * 8;
            uint32_t off = r * 128 + ((chk2 ^ (r & 7)) << 4);
            uint32_t t4[4];
            LDSM4(t4, sb + 32768 + ch * 8192 + off);
            bh[jp*2][0]   = t4[0]; bh[jp*2][1]   = t4[1];
            bh[jp*2+1][0] = t4[2]; bh[jp*2+1][1] = t4[3];
        }
        #pragma unroll
        for (int i = 0; i < 2; i++)
            #pragma unroll
            for (int j = 0; j < 4; j++)
                MMA(c[i][j], ah[i], bh[j]);
    }

    #pragma unroll
    for (int j = 0; j < 4; j++) {
        int col = wn0 + j * 8 + 2 * (lane & 3);
        float bz0 = b1s[col], bz1 = b1s[col + 1];
        float s0 = 0.f, q0 = 0.f, s1 = 0.f, q1 = 0.f;
        #pragma unroll
        for (int i = 0; i < 2; i++) {
            int row = m0 + wm0 + i * 16 + (lane >> 2);
            float a0 = fmaxf(c[i][j][0] + bz0, 0.f);
            float a1 = fmaxf(c[i][j][1] + bz1, 0.f);
            float a2 = fmaxf(c[i][j][2] + bz0, 0.f);
            float a3 = fmaxf(c[i][j][3] + bz1, 0.f);
            *(__half2*)&g_Ah[(size_t)row * 64 + col]       = __floats2half2_rn(a0, a1);
            *(__half2*)&g_Ah[(size_t)(row + 8) * 64 + col] = __floats2half2_rn(a2, a3);
            s0 += a0 + a2; q0 += a0 * a0 + a2 * a2;
            s1 += a1 + a3; q1 += a1 * a1 + a3 * a3;
        }
        #pragma unroll
        for (int off = 4; off <= 16; off <<= 1) {
            s0 += __shfl_xor_sync(0xffffffff, s0, off);
            q0 += __shfl_xor_sync(0xffffffff, q0, off);
            s1 += __shfl_xor_sync(0xffffffff, s1, off);
            q1 += __shfl_xor_sync(0xffffffff, q1, off);
        }
        if (lane < 4) {
            atomicAdd(&sacc[col], s0); atomicAdd(&qacc[col], q0);
            atomicAdd(&sacc[col + 1], s1); atomicAdd(&qacc[col + 1], q1);
        }
    }
    __syncthreads();
    if (tid < 64) {
        atomicAdd(&g_stats[tid],      sacc[tid]);
        atomicAdd(&g_stats[64 + tid], qacc[tid]);
    }
}

// ===================== K4: finalize BN, fold into W2 =====================
__global__ void finalize_kernel(const float* __restrict__ gamma,
                                const float* __restrict__ beta,
                                const float* __restrict__ W2,
                                const float* __restrict__ b2) {
    __shared__ float red0[64], red1[64];
    int j = threadIdx.x;
    float mu  = g_stats[j]      * (1.f / BATCH);
    float var = g_stats[64 + j] * (1.f / BATCH) - mu * mu;
    float inv = rsqrtf(var + 1e-5f);
    float gsc = gamma[j] * inv;
    float w0 = W2[j], w1 = W2[64 + j];
    g_W2e[2 * j]     = w0 * gsc;
    g_W2e[2 * j + 1] = w1 * gsc;
    float c = beta[j] - mu * gsc;
    red0[j] = c * w0;
    red1[j] = c * w1;
    __syncthreads();
    if (j == 0) { float s = 0.f; for (int i = 0; i < 64; i++) s += red0[i]; g_be[0] = b2[0] + s; }
    if (j == 1) { float s = 0.f; for (int i = 0; i < 64; i++) s += red1[i]; g_be[1] = b2[1] + s; }
}

// ===================== K5: output = A @ W2e + be =====================
__global__ __launch_bounds__(256) void out_kernel(float* __restrict__ out) {
    __shared__ float w2s[128];
    __shared__ float bes[2];
    int tid = threadIdx.x;
    if (tid < 128) w2s[tid] = g_W2e[tid];
    if (tid < 2)   bes[tid] = g_be[tid];
    __syncthreads();
    int b = blockIdx.x * 256 + tid;
    const __half2* ar = (const __half2*)(g_Ah + (size_t)b * 64);
    float o0 = bes[0], o1 = bes[1];
    #pragma unroll
    for (int q = 0; q < 32; q++) {
        float2 v = __half22float2(ar[q]);
        o0 += v.x * w2s[4 * q]     + v.y * w2s[4 * q + 2];
        o1 += v.x * w2s[4 * q + 1] + v.y * w2s[4 * q + 3];
    }
    ((float2*)out)[b] = make_float2(o0, o1);
}

// ===================== launcher =====================
extern "C" void kernel_launch(void* const* d_in, const int* in_sizes, int n_in,
                              void* d_out, int out_size) {
    const int*   n_id        = (const int*)  d_in[0];
    const float* memory      = (const float*)d_in[1];
    const int*   last_update = (const int*)  d_in[2];
    const int*   store_src   = (const int*)  d_in[3];
    const int*   store_dst   = (const int*)  d_in[4];
    const int*   store_t     = (const int*)  d_in[5];
    const float* store_msg   = (const float*)d_in[6];
    const float* time_w      = (const float*)d_in[7];
    const float* time_b      = (const float*)d_in[8];
    const float* W_ih        = (const float*)d_in[9];
    const float* b_ih        = (const float*)d_in[10];
    const float* W_hh        = (const float*)d_in[11];
    const float* b_hh        = (const float*)d_in[12];
    const float* W1          = (const float*)d_in[13];
    const float* b1          = (const float*)d_in[14];
    const float* gamma       = (const float*)d_in[15];
    const float* beta        = (const float*)d_in[16];
    const float* W2          = (const float*)d_in[17];
    const float* b2          = (const float*)d_in[18];
    float*       out         = (float*)d_out;

    cudaFuncSetAttribute(gemm_kernel, cudaFuncAttributeMaxDynamicSharedMemorySize, SMEM_TOT);
    cudaFuncSetAttribute(w1bn_kernel, cudaFuncAttributeMaxDynamicSharedMemorySize, WSM_TOT);

    prep_kernel<<<(NP * KP + 255) / 256, 256>>>(W_ih, W_hh, b_ih, b_hh, W1);
    assemble_kernel<<<BATCH / 8, 256>>>(n_id, memory, last_update, store_src,
                                        store_dst, store_t, store_msg, time_w, time_b);
    gemm_kernel<<<dim3(5, BATCH / BMM), 256, SMEM_TOT>>>();
    w1bn_kernel<<<BATCH / 128, 256, WSM_TOT>>>(b1);
    finalize_kernel<<<1, 64>>>(gamma, beta, W2, b2);
    out_kernel<<<BATCH / 256, 256>>>(out);
}